// round 7
// baseline (speedup 1.0000x reference)
#include <cuda_runtime.h>
#include <cuda_fp16.h>

// Problem constants (match reference)
#define BB 32
#define LL 4096
#define DD 128
#define NN1 4      // N-1 context slots
#define VV 128

// fp16 lookup table: T[k][tok][v], 4*128*128 halves = 128 KB (L1-resident).
// Bias is pre-folded into the k=0 slice.
__device__ __half g_Th[NN1 * VV * VV];

// ---------------------------------------------------------------------------
// Kernel 1: T[k][tok][v] = sum_d emb[tok][d] * W[v][k*128+d]  (+ b[v] at k=0)
// grid = (8 v-groups, 16 tok-groups, 4 k) = 512 blocks, 128 threads.
// Calls the PDL trigger at entry so the dependent ngram kernel's prologue
// overlaps with this kernel's execution.
// ---------------------------------------------------------------------------
#define VPB 16      // v-rows per block
#define TPB 8       // toks per block
#define WPAD 4      // smem row pad (floats)

__global__ void __launch_bounds__(128)
build_table_kernel(const float* __restrict__ emb,
                   const float* __restrict__ W,
                   const float* __restrict__ bvec) {
    cudaTriggerProgrammaticLaunchCompletion();   // release dependent launch early

    const int v0   = blockIdx.x * VPB;
    const int tok0 = blockIdx.y * TPB;
    const int k    = blockIdx.z;

    __shared__ float sw[VPB][DD + WPAD];
    __shared__ float e[TPB][DD + WPAD];

#pragma unroll
    for (int i = 0; i < 4; i++) {
        int idx = i * 128 + threadIdx.x;           // 0..511
        int vi  = idx >> 5;                        // 32 float4 per row
        int c   = idx & 31;
        const float4* wsrc = reinterpret_cast<const float4*>(
            W + (size_t)(v0 + vi) * (NN1 * DD) + k * DD);
        *reinterpret_cast<float4*>(&sw[vi][c * 4]) = __ldg(&wsrc[c]);
    }
    {
        const float4* esrc = reinterpret_cast<const float4*>(emb + (size_t)tok0 * DD);
#pragma unroll
        for (int i = 0; i < 2; i++) {
            int idx = i * 128 + threadIdx.x;       // 0..255
            float4 ev = __ldg(&esrc[idx]);
            int t = idx >> 5;
            int c = idx & 31;
            *reinterpret_cast<float4*>(&e[t][c * 4]) = ev;
        }
    }
    __syncthreads();

    const int vi = threadIdx.x >> 3;               // 0..15
    const int tp = threadIdx.x & 7;                // 0..7

    float acc = 0.0f;
#pragma unroll
    for (int d = 0; d < DD; d += 4) {
        float4 w  = *reinterpret_cast<const float4*>(&sw[vi][d]);
        float4 ea = *reinterpret_cast<const float4*>(&e[tp][d]);
        acc += w.x * ea.x + w.y * ea.y + w.z * ea.z + w.w * ea.w;
    }
    if (k == 0) acc += __ldg(&bvec[v0 + vi]);

    g_Th[(k * VV + tok0 + tp) * VV + v0 + vi] = __float2half_rn(acc);
}

// ---------------------------------------------------------------------------
// Kernel 2: gather-sum (round-5 shape: one warp per 2 consecutive positions,
// 8 warps/CTA, 8192 CTAs, occ ~78%). PDL: everything not depending on the
// table (decode, token loads, bias-only path) runs before
// cudaGridDependencySynchronize(); table loads run after it.
// ---------------------------------------------------------------------------
__device__ __forceinline__ float4 combine4(const uint2& u0, const uint2& u1,
                                           const uint2& u2, const uint2& u3) {
    __half2 lo = __hadd2(__hadd2(*(const __half2*)&u0.x, *(const __half2*)&u1.x),
                         __hadd2(*(const __half2*)&u2.x, *(const __half2*)&u3.x));
    __half2 hi = __hadd2(__hadd2(*(const __half2*)&u0.y, *(const __half2*)&u1.y),
                         __hadd2(*(const __half2*)&u2.y, *(const __half2*)&u3.y));
    float2 flo = __half22float2(lo);
    float2 fhi = __half22float2(hi);
    return make_float4(flo.x, flo.y, fhi.x, fhi.y);
}

__global__ void __launch_bounds__(256)
ngram_sum_kernel(const int* __restrict__ x,
                 const float* __restrict__ bvec,
                 float* __restrict__ out) {
    const int warp = blockIdx.x * (blockDim.x >> 5) + (threadIdx.x >> 5);
    const int lane = threadIdx.x & 31;
    const int pos0 = warp << 1;                 // two consecutive positions
    const int b  = pos0 >> 12;                  // / 4096
    const int j0 = pos0 & (LL - 1);             // % 4096 (even)

    float4* o = reinterpret_cast<float4*>(out + (size_t)pos0 * VV);

    if (j0 < NN1) {                             // j0 in {0,2}: bias only
        float4 bb = reinterpret_cast<const float4*>(bvec)[lane];
        o[lane]      = bb;
        o[32 + lane] = bb;
        return;                                 // no table dependency
    }

    // Token loads: independent of the table -> overlap with producer kernel.
    const int* xr = x + b * LL + (j0 - NN1);
    const int t0 = __ldg(xr + 0);
    const int t1 = __ldg(xr + 1);
    const int t2 = __ldg(xr + 2);
    const int t3 = __ldg(xr + 3);
    const int t4 = __ldg(xr + 4);

    // Wait for build_table_kernel completion (table visible after this).
    cudaGridDependencySynchronize();

    const uint2* T = reinterpret_cast<const uint2*>(g_Th);   // 32 uint2 per row
    // position j0: tokens t0..t3; position j0+1: tokens t1..t4
    uint2 a0 = __ldg(&T[((0 * VV + t0) << 5) + lane]);
    uint2 a1 = __ldg(&T[((1 * VV + t1) << 5) + lane]);
    uint2 a2 = __ldg(&T[((2 * VV + t2) << 5) + lane]);
    uint2 a3 = __ldg(&T[((3 * VV + t3) << 5) + lane]);
    uint2 c0 = __ldg(&T[((0 * VV + t1) << 5) + lane]);
    uint2 c1 = __ldg(&T[((1 * VV + t2) << 5) + lane]);
    uint2 c2 = __ldg(&T[((2 * VV + t3) << 5) + lane]);
    uint2 c3 = __ldg(&T[((3 * VV + t4) << 5) + lane]);

    o[lane]      = combine4(a0, a1, a2, a3);
    o[32 + lane] = combine4(c0, c1, c2, c3);
}

// ---------------------------------------------------------------------------
// Launch. Inputs (metadata order): x(int32 B*L), emb(f32 V*D), W(f32 V*4D),
// b(f32 V). Output: f32 B*L*V.
// ngram is launched with ProgrammaticStreamSerialization so it overlaps with
// the tail of build_table (PDL); correctness is enforced by
// cudaGridDependencySynchronize() inside the kernel.
// ---------------------------------------------------------------------------
extern "C" void kernel_launch(void* const* d_in, const int* in_sizes, int n_in,
                              void* d_out, int out_size) {
    const int*   x    = (const int*)d_in[0];
    const float* emb  = (const float*)d_in[1];
    const float* W    = (const float*)d_in[2];
    const float* bvec = (const float*)d_in[3];
    float* out = (float*)d_out;

    dim3 bgrid(VV / VPB, VV / TPB, NN1);        // (8, 16, 4) = 512 blocks
    build_table_kernel<<<bgrid, 128>>>(emb, W, bvec);

    const int positions = BB * LL;              // 131072
    const int warps = positions / 2;            // 65536
    const int blocks = warps / 8;               // 8192 (8 warps/block, exact)

    cudaLaunchAttribute attrs[1];
    attrs[0].id = cudaLaunchAttributeProgrammaticStreamSerialization;
    attrs[0].val.programmaticStreamSerializationAllowed = 1;

    cudaLaunchConfig_t cfg = {};
    cfg.gridDim  = dim3(blocks, 1, 1);
    cfg.blockDim = dim3(256, 1, 1);
    cfg.dynamicSmemBytes = 0;
    cfg.stream = 0;                              // legacy default stream (captured)
    cfg.attrs = attrs;
    cfg.numAttrs = 1;

    cudaLaunchKernelEx(&cfg, ngram_sum_kernel, x, bvec, out);
}

// round 8
// speedup vs baseline: 1.0135x; 1.0135x over previous
#include <cuda_runtime.h>
#include <cuda_fp16.h>

// Problem constants (match reference)
#define BB 32
#define LL 4096
#define DD 128
#define NN1 4      // N-1 context slots
#define VV 128

// fp16 lookup table: T[k][tok][v], 4*128*128 halves = 128 KB (L1-resident).
// Bias is pre-folded into the k=0 slice.
__device__ __half g_Th[NN1 * VV * VV];

// ---------------------------------------------------------------------------
// Kernel 1: T[k][tok][v] = sum_d emb[tok][d] * W[v][k*128+d]  (+ b[v] at k=0)
// grid = (8 v-groups, 16 tok-groups, 4 k) = 512 blocks, 128 threads.
// ---------------------------------------------------------------------------
#define VPB 16      // v-rows per block
#define TPB 8       // toks per block
#define WPAD 4      // smem row pad (floats)

__global__ void __launch_bounds__(128)
build_table_kernel(const float* __restrict__ emb,
                   const float* __restrict__ W,
                   const float* __restrict__ bvec) {
    const int v0   = blockIdx.x * VPB;
    const int tok0 = blockIdx.y * TPB;
    const int k    = blockIdx.z;

    __shared__ float sw[VPB][DD + WPAD];
    __shared__ float e[TPB][DD + WPAD];

#pragma unroll
    for (int i = 0; i < 4; i++) {
        int idx = i * 128 + threadIdx.x;           // 0..511
        int vi  = idx >> 5;                        // 32 float4 per row
        int c   = idx & 31;
        const float4* wsrc = reinterpret_cast<const float4*>(
            W + (size_t)(v0 + vi) * (NN1 * DD) + k * DD);
        *reinterpret_cast<float4*>(&sw[vi][c * 4]) = __ldg(&wsrc[c]);
    }
    {
        const float4* esrc = reinterpret_cast<const float4*>(emb + (size_t)tok0 * DD);
#pragma unroll
        for (int i = 0; i < 2; i++) {
            int idx = i * 128 + threadIdx.x;       // 0..255
            float4 ev = __ldg(&esrc[idx]);
            int t = idx >> 5;
            int c = idx & 31;
            *reinterpret_cast<float4*>(&e[t][c * 4]) = ev;
        }
    }
    __syncthreads();

    const int vi = threadIdx.x >> 3;               // 0..15
    const int tp = threadIdx.x & 7;                // 0..7

    float acc = 0.0f;
#pragma unroll
    for (int d = 0; d < DD; d += 4) {
        float4 w  = *reinterpret_cast<const float4*>(&sw[vi][d]);
        float4 ea = *reinterpret_cast<const float4*>(&e[tp][d]);
        acc += w.x * ea.x + w.y * ea.y + w.z * ea.z + w.w * ea.w;
    }
    if (k == 0) acc += __ldg(&bvec[v0 + vi]);

    g_Th[(k * VV + tok0 + tp) * VV + v0 + vi] = __float2half_rn(acc);
}

// ---------------------------------------------------------------------------
// Kernel 2: gather-sum. CTA = 256 threads = 8 warps covers 16 consecutive
// positions of one batch row (16 | 4096, never crosses rows). The 20-token
// window x[j_base-4 .. j_base+15] is staged in smem ONCE per CTA (coalesced),
// removing the high-latency uniform token LDG from every warp's critical
// chain. Warps then issue 8 independent L1-resident table loads immediately.
// ---------------------------------------------------------------------------
__device__ __forceinline__ float4 combine4(const uint2& u0, const uint2& u1,
                                           const uint2& u2, const uint2& u3) {
    __half2 lo = __hadd2(__hadd2(*(const __half2*)&u0.x, *(const __half2*)&u1.x),
                         __hadd2(*(const __half2*)&u2.x, *(const __half2*)&u3.x));
    __half2 hi = __hadd2(__hadd2(*(const __half2*)&u0.y, *(const __half2*)&u1.y),
                         __hadd2(*(const __half2*)&u2.y, *(const __half2*)&u3.y));
    float2 flo = __half22float2(lo);
    float2 fhi = __half22float2(hi);
    return make_float4(flo.x, flo.y, fhi.x, fhi.y);
}

__global__ void __launch_bounds__(256)
ngram_sum_kernel(const int* __restrict__ x,
                 const float* __restrict__ bvec,
                 float* __restrict__ out) {
    __shared__ int sx[20];

    const int pos_base = blockIdx.x << 4;        // 16 positions per CTA
    const int b      = pos_base >> 12;           // batch row
    const int j_base = pos_base & (LL - 1);      // 0,16,32,... (row-aligned)

    // Stage token window: x[b][j_base-4 .. j_base+15] (clamped at row start;
    // clamped slots are only indexed by bias-only positions, never consumed).
    if (threadIdx.x < 20) {
        int off = j_base - NN1 + (int)threadIdx.x;
        if (off < 0) off = 0;
        sx[threadIdx.x] = __ldg(x + b * LL + off);
    }
    __syncthreads();

    const int wl   = threadIdx.x >> 5;           // warp in CTA: 0..7
    const int lane = threadIdx.x & 31;
    const int pos0 = pos_base + (wl << 1);       // two consecutive positions
    const int j0   = j_base + (wl << 1);

    float4* o = reinterpret_cast<float4*>(out + (size_t)pos0 * VV);

    if (j0 < NN1) {                              // j0 in {0,2}: bias only
        float4 bb = reinterpret_cast<const float4*>(bvec)[lane];
        o[lane]      = bb;
        o[32 + lane] = bb;
        return;
    }

    // Tokens for pos0: sx[2*wl .. 2*wl+3]; pos0+1 additionally needs sx[2*wl+4].
    const int t0 = sx[(wl << 1) + 0];
    const int t1 = sx[(wl << 1) + 1];
    const int t2 = sx[(wl << 1) + 2];
    const int t3 = sx[(wl << 1) + 3];
    const int t4 = sx[(wl << 1) + 4];

    const uint2* T = reinterpret_cast<const uint2*>(g_Th);   // 32 uint2 per row
    uint2 a0 = __ldg(&T[((0 * VV + t0) << 5) + lane]);
    uint2 a1 = __ldg(&T[((1 * VV + t1) << 5) + lane]);
    uint2 a2 = __ldg(&T[((2 * VV + t2) << 5) + lane]);
    uint2 a3 = __ldg(&T[((3 * VV + t3) << 5) + lane]);
    uint2 c0 = __ldg(&T[((0 * VV + t1) << 5) + lane]);
    uint2 c1 = __ldg(&T[((1 * VV + t2) << 5) + lane]);
    uint2 c2 = __ldg(&T[((2 * VV + t3) << 5) + lane]);
    uint2 c3 = __ldg(&T[((3 * VV + t4) << 5) + lane]);

    o[lane]      = combine4(a0, a1, a2, a3);
    o[32 + lane] = combine4(c0, c1, c2, c3);
}

// ---------------------------------------------------------------------------
// Launch. Inputs (metadata order): x(int32 B*L), emb(f32 V*D), W(f32 V*4D),
// b(f32 V). Output: f32 B*L*V.
// ---------------------------------------------------------------------------
extern "C" void kernel_launch(void* const* d_in, const int* in_sizes, int n_in,
                              void* d_out, int out_size) {
    const int*   x    = (const int*)d_in[0];
    const float* emb  = (const float*)d_in[1];
    const float* W    = (const float*)d_in[2];
    const float* bvec = (const float*)d_in[3];
    float* out = (float*)d_out;

    dim3 bgrid(VV / VPB, VV / TPB, NN1);        // (8, 16, 4) = 512 blocks
    build_table_kernel<<<bgrid, 128>>>(emb, W, bvec);

    const int positions = BB * LL;              // 131072
    const int blocks = positions / 16;          // 8192 CTAs, 16 pos each
    ngram_sum_kernel<<<blocks, 256>>>(x, bvec, out);
}